// round 5
// baseline (speedup 1.0000x reference)
#include <cuda_runtime.h>

#define EPS 1e-8f

namespace {
constexpr int B = 256;
constexpr int S = 24;
constexpr int D = 256;
constexpr int N = 8192;
constexpr int T = 512;           // threads per block
constexpr int F4 = N / 4 / T;    // float4s per thread = 4
}

// ---------------------------------------------------------------------------
// Fused kernel: grid = (S+1, B), 512 threads, 4 blocks/SM (regs forced <=32).
//   blockIdx.x == i in [0,S): output row (b,i) of new_patch_attn.
//   blockIdx.x == S:          new_slots + slot_nums for batch b (smem-only).
// ---------------------------------------------------------------------------
__global__ void __launch_bounds__(T, 4) fused_kernel(
    const float* __restrict__ slots,     // [B,S,D]
    const float* __restrict__ pa,        // [B,S,N]
    const int* __restrict__ clusters,    // [B,S] int32
    float* __restrict__ out_slots,       // [B,S,D]
    float* __restrict__ out_attn,        // [B,S,N]
    float* __restrict__ out_nums)        // [B]
{
    const int i = blockIdx.x;
    const int b = blockIdx.y;
    const int t = threadIdx.x;

    __shared__ int   cls[S];
    __shared__ int   list[S];
    __shared__ int   mcnt;
    __shared__ float wsum[T / 32];
    __shared__ float stile[S * D];   // 24KB, used only by the slots path

    if (t < S) cls[t] = clusters[b * S + t];

    // ------------------------------------------------------------------
    // Slots path: one block per batch. All state lives in smem.
    // ------------------------------------------------------------------
    if (i == S) {
        for (int idx = t; idx < S * D; idx += T)
            stile[idx] = slots[(size_t)b * S * D + idx];
        __syncthreads();

        if (t < D) {
            const int d = t;
            float* ob = out_slots + (size_t)b * S * D + d;
            #pragma unroll
            for (int ii = 0; ii < S; ii++) {
                float acc = 0.0f;
                int c = 0;
                #pragma unroll
                for (int j = 0; j < S; j++) {
                    bool hit = (cls[j] == ii);
                    if (hit) acc += stile[j * D + d];
                    c += hit;
                }
                ob[ii * D] = acc / ((float)c + EPS);
            }
            if (d == 0) {
                int n = 0;
                #pragma unroll
                for (int ii = 0; ii < S; ii++) {
                    int c = 0;
                    #pragma unroll
                    for (int j = 0; j < S; j++) c += (cls[j] == ii);
                    n += (c > 0);
                }
                out_nums[b] = (float)n;
            }
        }
        return;
    }

    // ------------------------------------------------------------------
    // Attn path: segment-sum + EPS + row-normalize for output row (b,i)
    // ------------------------------------------------------------------
    __syncthreads();   // cls[] visible
    if (t == 0) {
        int m = 0;
        #pragma unroll
        for (int j = 0; j < S; j++)
            if (cls[j] == i) list[m++] = j;
        mcnt = m;
    }
    __syncthreads();
    const int m = mcnt;

    const float4* base = (const float4*)(pa + (size_t)b * S * N) + t;

    float4 acc[F4];
    #pragma unroll
    for (int k = 0; k < F4; k++) acc[k] = make_float4(EPS, EPS, EPS, EPS);

    for (int r = 0; r < m; r++) {
        const float4* row = base + (size_t)list[r] * (N / 4);
        #pragma unroll
        for (int k = 0; k < F4; k++) {
            float4 v = __ldcs(row + k * T);
            acc[k].x += v.x; acc[k].y += v.y;
            acc[k].z += v.z; acc[k].w += v.w;
        }
    }

    // Row normalizer: warp partials -> smem -> every thread sums 16 partials.
    float ls = 0.0f;
    #pragma unroll
    for (int k = 0; k < F4; k++)
        ls += (acc[k].x + acc[k].y) + (acc[k].z + acc[k].w);
    #pragma unroll
    for (int off = 16; off > 0; off >>= 1)
        ls += __shfl_xor_sync(0xFFFFFFFFu, ls, off);
    if ((t & 31) == 0) wsum[t >> 5] = ls;
    __syncthreads();

    float tot = 0.0f;
    #pragma unroll
    for (int k = 0; k < T / 32; k++) tot += wsum[k];   // broadcast reads
    const float inv = 1.0f / tot;

    float4* o = (float4*)(out_attn + (size_t)(b * S + i) * N) + t;
    #pragma unroll
    for (int k = 0; k < F4; k++) {
        float4 r = make_float4(acc[k].x * inv, acc[k].y * inv,
                               acc[k].z * inv, acc[k].w * inv);
        __stcs(o + k * T, r);
    }
}

// ---------------------------------------------------------------------------
extern "C" void kernel_launch(void* const* d_in, const int* in_sizes, int n_in,
                              void* d_out, int out_size)
{
    const float* slots    = (const float*)d_in[0];   // [B,S,D]
    const float* pa       = (const float*)d_in[1];   // [B,S,N]
    const int*   clusters = (const int*)d_in[2];     // [B,S] int32

    float* out = (float*)d_out;
    float* out_slots = out;                              // [B,S,D]
    float* out_attn  = out + (size_t)B * S * D;          // [B,S,N]
    float* out_nums  = out_attn + (size_t)B * S * N;     // [B]

    fused_kernel<<<dim3(S + 1, B), T>>>(slots, pa, clusters,
                                        out_slots, out_attn, out_nums);
}

// round 7
// speedup vs baseline: 1.0004x; 1.0004x over previous
#include <cuda_runtime.h>

#define EPS 1e-8f

namespace {
constexpr int B = 256;
constexpr int S = 24;
constexpr int D = 256;
constexpr int N = 8192;
constexpr int T = 512;           // threads per block (hot kernel)
constexpr int F4 = N / 4 / T;    // float4s per thread = 4
}

// Packed member lists: per (b,i), 24 x 5-bit slot indices (6 per 32-bit word),
// sentinel 31 terminates. 6144 * 16B = 96KB -> stays L2-resident.
__device__ uint4 g_packed[B * S];

// ---------------------------------------------------------------------------
// Setup kernel: new_slots + slot_nums + packed member lists.
// grid = B, 256 threads.
// ---------------------------------------------------------------------------
__global__ void __launch_bounds__(256) setup_kernel(
    const float* __restrict__ slots,     // [B,S,D]
    const int* __restrict__ clusters,    // [B,S] int32
    float* __restrict__ out_slots,       // [B,S,D]
    float* __restrict__ out_nums)        // [B]
{
    const int b = blockIdx.x;
    const int t = threadIdx.x;

    __shared__ int   cls[S];
    __shared__ float stile[S * D];

    if (t < S) cls[t] = clusters[b * S + t];
    for (int idx = t; idx < S * D; idx += 256)
        stile[idx] = slots[(size_t)b * S * D + idx];
    __syncthreads();

    // new_slots: thread t = dim d (D == 256 == blockDim)
    {
        const int d = t;
        float* ob = out_slots + (size_t)b * S * D + d;
        #pragma unroll
        for (int ii = 0; ii < S; ii++) {
            float acc = 0.0f;
            int c = 0;
            #pragma unroll
            for (int j = 0; j < S; j++) {
                bool hit = (cls[j] == ii);
                if (hit) acc += stile[j * D + d];
                c += hit;
            }
            ob[ii * D] = acc / ((float)c + EPS);
        }
    }

    // slot_nums
    if (t == 0) {
        int n = 0;
        #pragma unroll
        for (int ii = 0; ii < S; ii++) {
            int c = 0;
            #pragma unroll
            for (int j = 0; j < S; j++) c += (cls[j] == ii);
            n += (c > 0);
        }
        out_nums[b] = (float)n;
    }

    // Packed member list for cluster i = t
    if (t < S) {
        unsigned w[4] = {0u, 0u, 0u, 0u};
        int m = 0;
        #pragma unroll
        for (int j = 0; j < S; j++) {
            if (cls[j] == t) {
                w[m / 6] |= (unsigned)j << (5 * (m % 6));
                m++;
            }
        }
        for (int r = m; r < S; r++)
            w[r / 6] |= 31u << (5 * (r % 6));
        g_packed[b * S + t] = make_uint4(w[0], w[1], w[2], w[3]);
    }
}

// ---------------------------------------------------------------------------
// Hot kernel: new_patch_attn. grid = (S, B), 512 threads, 4 blocks/SM.
// One broadcast __ldg of the packed list, then straight into row loads.
// ---------------------------------------------------------------------------
__global__ void __launch_bounds__(T, 4) attn_kernel(
    const float* __restrict__ pa,        // [B,S,N]
    float* __restrict__ out_attn)        // [B,S,N]
{
    const int i = blockIdx.x;
    const int b = blockIdx.y;
    const int t = threadIdx.x;

    __shared__ float wsum[T / 32];

    const uint4 pk = __ldg(&g_packed[b * S + i]);
    unsigned w[4] = {pk.x, pk.y, pk.z, pk.w};

    const float4* base = (const float4*)pa + (size_t)b * (S * N / 4) + t;

    float4 acc[F4];
    #pragma unroll
    for (int k = 0; k < F4; k++) acc[k] = make_float4(EPS, EPS, EPS, EPS);

    #pragma unroll
    for (int r = 0; r < S; r++) {
        const int idx = (int)((w[r / 6] >> (5 * (r % 6))) & 31u);
        if (idx >= S) break;   // sentinel: no more members
        const float4* row = base + idx * (N / 4);
        #pragma unroll
        for (int k = 0; k < F4; k++) {
            float4 v = __ldcs(row + k * T);
            acc[k].x += v.x; acc[k].y += v.y;
            acc[k].z += v.z; acc[k].w += v.w;
        }
    }

    // Row normalizer
    float ls = 0.0f;
    #pragma unroll
    for (int k = 0; k < F4; k++)
        ls += (acc[k].x + acc[k].y) + (acc[k].z + acc[k].w);
    #pragma unroll
    for (int off = 16; off > 0; off >>= 1)
        ls += __shfl_xor_sync(0xFFFFFFFFu, ls, off);
    if ((t & 31) == 0) wsum[t >> 5] = ls;
    __syncthreads();

    float tot = 0.0f;
    #pragma unroll
    for (int k = 0; k < T / 32; k++) tot += wsum[k];   // broadcast reads
    const float inv = 1.0f / tot;

    float4* o = (float4*)out_attn + (size_t)(b * S + i) * (N / 4) + t;
    #pragma unroll
    for (int k = 0; k < F4; k++) {
        float4 r = make_float4(acc[k].x * inv, acc[k].y * inv,
                               acc[k].z * inv, acc[k].w * inv);
        __stcs(o + k * T, r);
    }
}

// ---------------------------------------------------------------------------
extern "C" void kernel_launch(void* const* d_in, const int* in_sizes, int n_in,
                              void* d_out, int out_size)
{
    const float* slots    = (const float*)d_in[0];   // [B,S,D]
    const float* pa       = (const float*)d_in[1];   // [B,S,N]
    const int*   clusters = (const int*)d_in[2];     // [B,S] int32

    float* out = (float*)d_out;
    float* out_slots = out;                              // [B,S,D]
    float* out_attn  = out + (size_t)B * S * D;          // [B,S,N]
    float* out_nums  = out_attn + (size_t)B * S * N;     // [B]

    setup_kernel<<<B, 256>>>(slots, clusters, out_slots, out_nums);
    attn_kernel<<<dim3(S, B), T>>>(pa, out_attn);
}

// round 8
// speedup vs baseline: 1.1150x; 1.1146x over previous
#include <cuda_runtime.h>

#define EPS 1e-8f

namespace {
constexpr int B = 256;
constexpr int S = 24;
constexpr int D = 256;
constexpr int N = 8192;
constexpr int T = 512;           // threads per block (hot kernel)
constexpr int F4 = N / 4 / T;    // float4s per thread = 4
}

// Packed member lists: per (b,i), 24 x 5-bit slot indices (6 per 32-bit word),
// sentinel 31 terminates. 6144 * 16B = 96KB -> stays L2-resident.
__device__ uint4 g_packed[B * S];

// ---------------------------------------------------------------------------
// Pack kernel: member lists + slot_nums. grid = B, 32 threads (one warp).
// Pure warp-shuffle: no smem, no barriers. ~2-3us total.
// ---------------------------------------------------------------------------
__global__ void __launch_bounds__(32) pack_kernel(
    const int* __restrict__ clusters,    // [B,S] int32
    float* __restrict__ out_nums)        // [B]
{
    const int b = blockIdx.x;
    const int t = threadIdx.x;

    int cl = (t < S) ? clusters[b * S + t] : -1;

    int m = 0;
    unsigned w[4] = {0u, 0u, 0u, 0u};
    #pragma unroll
    for (int j = 0; j < S; j++) {
        int cj = __shfl_sync(0xFFFFFFFFu, cl, j);
        if (t < S && cj == t) {
            w[m / 6] |= (unsigned)j << (5 * (m % 6));
            m++;
        }
    }
    if (t < S) {
        for (int r = m; r < S; r++)
            w[r / 6] |= 31u << (5 * (r % 6));
        g_packed[b * S + t] = make_uint4(w[0], w[1], w[2], w[3]);
    }

    unsigned nz = __ballot_sync(0xFFFFFFFFu, (t < S) && (m > 0));
    if (t == 0) out_nums[b] = (float)__popc(nz);
}

// ---------------------------------------------------------------------------
// Slots kernel: new_slots. grid = (S, B), 64 threads (one float4 per thread).
// Same structure as the hot kernel: broadcast list load -> row sums.
// ---------------------------------------------------------------------------
__global__ void __launch_bounds__(64) slots_kernel(
    const float* __restrict__ slots,     // [B,S,D]
    float* __restrict__ out_slots)       // [B,S,D]
{
    const int i = blockIdx.x;
    const int b = blockIdx.y;
    const int t = threadIdx.x;           // 0..63 -> float4 index in D

    const uint4 pk = __ldg(&g_packed[b * S + i]);
    unsigned w[4] = {pk.x, pk.y, pk.z, pk.w};

    const float4* base = (const float4*)slots + (size_t)b * (S * D / 4) + t;

    float4 acc = make_float4(0.f, 0.f, 0.f, 0.f);
    int m = 0;
    #pragma unroll
    for (int r = 0; r < S; r++) {
        const int idx = (int)((w[r / 6] >> (5 * (r % 6))) & 31u);
        if (idx >= S) break;
        float4 v = __ldg(base + idx * (D / 4));
        acc.x += v.x; acc.y += v.y; acc.z += v.z; acc.w += v.w;
        m++;
    }

    const float inv = 1.0f / ((float)m + EPS);
    float4 r4 = make_float4(acc.x * inv, acc.y * inv, acc.z * inv, acc.w * inv);
    ((float4*)out_slots)[(size_t)(b * S + i) * (D / 4) + t] = r4;
}

// ---------------------------------------------------------------------------
// Hot kernel: new_patch_attn. grid = (S, B), 512 threads, 4 blocks/SM.
// ---------------------------------------------------------------------------
__global__ void __launch_bounds__(T, 4) attn_kernel(
    const float* __restrict__ pa,        // [B,S,N]
    float* __restrict__ out_attn)        // [B,S,N]
{
    const int i = blockIdx.x;
    const int b = blockIdx.y;
    const int t = threadIdx.x;

    __shared__ float wsum[T / 32];

    const uint4 pk = __ldg(&g_packed[b * S + i]);
    unsigned w[4] = {pk.x, pk.y, pk.z, pk.w};

    const float4* base = (const float4*)pa + (size_t)b * (S * N / 4) + t;

    float4 acc[F4];
    #pragma unroll
    for (int k = 0; k < F4; k++) acc[k] = make_float4(EPS, EPS, EPS, EPS);

    #pragma unroll
    for (int r = 0; r < S; r++) {
        const int idx = (int)((w[r / 6] >> (5 * (r % 6))) & 31u);
        if (idx >= S) break;   // sentinel: no more members
        const float4* row = base + idx * (N / 4);
        #pragma unroll
        for (int k = 0; k < F4; k++) {
            float4 v = __ldcs(row + k * T);
            acc[k].x += v.x; acc[k].y += v.y;
            acc[k].z += v.z; acc[k].w += v.w;
        }
    }

    // Row normalizer
    float ls = 0.0f;
    #pragma unroll
    for (int k = 0; k < F4; k++)
        ls += (acc[k].x + acc[k].y) + (acc[k].z + acc[k].w);
    #pragma unroll
    for (int off = 16; off > 0; off >>= 1)
        ls += __shfl_xor_sync(0xFFFFFFFFu, ls, off);
    if ((t & 31) == 0) wsum[t >> 5] = ls;
    __syncthreads();

    float tot = 0.0f;
    #pragma unroll
    for (int k = 0; k < T / 32; k++) tot += wsum[k];   // broadcast reads
    const float inv = 1.0f / tot;

    float4* o = (float4*)out_attn + (size_t)(b * S + i) * (N / 4) + t;
    #pragma unroll
    for (int k = 0; k < F4; k++) {
        float4 r = make_float4(acc[k].x * inv, acc[k].y * inv,
                               acc[k].z * inv, acc[k].w * inv);
        __stcs(o + k * T, r);
    }
}

// ---------------------------------------------------------------------------
extern "C" void kernel_launch(void* const* d_in, const int* in_sizes, int n_in,
                              void* d_out, int out_size)
{
    const float* slots    = (const float*)d_in[0];   // [B,S,D]
    const float* pa       = (const float*)d_in[1];   // [B,S,N]
    const int*   clusters = (const int*)d_in[2];     // [B,S] int32

    float* out = (float*)d_out;
    float* out_slots = out;                              // [B,S,D]
    float* out_attn  = out + (size_t)B * S * D;          // [B,S,N]
    float* out_nums  = out_attn + (size_t)B * S * N;     // [B]

    pack_kernel<<<B, 32>>>(clusters, out_nums);
    slots_kernel<<<dim3(S, B), 64>>>(slots, out_slots);
    attn_kernel<<<dim3(S, B), T>>>(pa, out_attn);
}